// round 13
// baseline (speedup 1.0000x reference)
#include <cuda_runtime.h>
#include <math.h>

#define T_LEN    4096
#define NTHREADS 256
#define NSEG     4               // segments of 1024 elements
#define NWARPS   (NTHREADS / 32)
#define FULL     0xFFFFFFFFu

__global__ __launch_bounds__(NTHREADS, 6)
void garch_kernel(const float4* __restrict__ x4,
                  const float* __restrict__ omega_log,
                  const float* __restrict__ alpha_log,
                  const float* __restrict__ beta_log,
                  float4* __restrict__ out4)
{
    __shared__ float BwS[NSEG][NWARPS];   // per-segment per-warp B aggregates
    __shared__ float sumw[NWARPS], sqw[NWARPS];

    const int tid  = threadIdx.x;
    const int lane = tid & 31;
    const int wid  = tid >> 5;

    // ---- scalar params ----
    const float ea    = expf(alpha_log[0]);
    const float eb    = expf(beta_log[0]);
    const float denom = 1.0f + ea + eb;
    const float omega = expf(omega_log[0]);
    const float alpha = ea / denom;
    const float beta  = eb / denom;

    // powers of beta by repeated squaring (scan multipliers; die after scan)
    float m0 = beta * beta;  m0 = m0 * m0;      // beta^4
    const float m1 = m0 * m0;                   // beta^8
    const float m2 = m1 * m1;                   // beta^16
    const float m3 = m2 * m2;                   // beta^32
    const float m4 = m3 * m3;                   // beta^64
    const float p128_1 = m4 * m4;               // beta^128
    const float p128_2 = p128_1 * p128_1;       // beta^256
    const float p128_4 = p128_2 * p128_2;       // beta^512
    const float beta1024 = p128_4 * p128_4;     // beta^1024

    // a_exc = beta^(4*lane), a_tot = beta^(4*tid)  (MUFU path; ~1e-6 rel on tiny terms)
    const float lnb   = __logf(beta);
    const float a_exc = __expf((float)(4 * lane) * lnb);
    const float a_tot = __expf((float)(4 * tid)  * lnb);

    // ---- load: 4 coalesced float4 per thread (the float4 IS the chunk) ----
    const size_t row4 = (size_t)blockIdx.x * (NSEG * NTHREADS);
    float4 v[NSEG];
    #pragma unroll
    for (int j = 0; j < NSEG; j++)
        v[j] = __ldcs(&x4[row4 + j * NTHREADS + tid]);

    // ---- variance partials + c_t = alpha*x_t^2 + omega ----
    float c[NSEG][4];
    float sum = 0.0f, sq = 0.0f;
    #pragma unroll
    for (int j = 0; j < NSEG; j++) {
        float xs[4] = { v[j].x, v[j].y, v[j].z, v[j].w };
        #pragma unroll
        for (int k = 0; k < 4; k++) {
            float x2 = xs[k] * xs[k];
            sum += xs[k];
            sq  += x2;
            c[j][k] = fmaf(alpha, x2, omega);
        }
    }
    #pragma unroll
    for (int off = 16; off > 0; off >>= 1) {
        sum += __shfl_xor_sync(FULL, sum, off);
        sq  += __shfl_xor_sync(FULL, sq,  off);
    }
    if (lane == 0) { sumw[wid] = sum; sqw[wid] = sq; }

    // ---- per-segment local B over 4 steps (A = beta^4, constant) ----
    float B[NSEG];
    #pragma unroll
    for (int j = 0; j < NSEG; j++) {
        float b = c[j][0];
        b = fmaf(beta, b, c[j][1]);
        b = fmaf(beta, b, c[j][2]);
        b = fmaf(beta, b, c[j][3]);
        B[j] = b;
    }

    // ---- B-only warp scans, constant multiplier per step: beta^(4*off) ----
    {
        const float mult[5] = { m0, m1, m2, m3, m4 };
        #pragma unroll
        for (int i = 0; i < 5; i++) {
            const int off = 1 << i;
            float bu[NSEG];
            #pragma unroll
            for (int j = 0; j < NSEG; j++)
                bu[j] = __shfl_up_sync(FULL, B[j], off);
            if (lane >= off) {
                #pragma unroll
                for (int j = 0; j < NSEG; j++)
                    B[j] = fmaf(mult[i], bu[j], B[j]);
            }
        }
    }
    if (lane == 31) {
        #pragma unroll
        for (int j = 0; j < NSEG; j++) BwS[j][wid] = B[j];
    }
    __syncthreads();             // the ONLY block barrier

    // ---- redundant per-warp cross-warp combine (no second barrier, no idle warps) ----
    const int seg = lane >> 3;   // which segment this lane's aggregate belongs to
    const int l8  = lane & 7;    // warp index within the segment
    float bag = BwS[seg][l8];    // 32 distinct floats -> conflict-free LDS

    float ts = (lane < NWARPS) ? sumw[lane] : 0.0f;
    float tq = (lane < NWARPS) ? sqw[lane]  : 0.0f;

    // interleave: 3-step 8-group B scan + 3-level variance xor reduce
    float bu;
    bu = __shfl_up_sync(FULL, bag, 1); if (l8 >= 1) bag = fmaf(p128_1, bu, bag);
    ts += __shfl_xor_sync(FULL, ts, 4); tq += __shfl_xor_sync(FULL, tq, 4);
    bu = __shfl_up_sync(FULL, bag, 2); if (l8 >= 2) bag = fmaf(p128_2, bu, bag);
    ts += __shfl_xor_sync(FULL, ts, 2); tq += __shfl_xor_sync(FULL, tq, 2);
    bu = __shfl_up_sync(FULL, bag, 4); if (l8 >= 4) bag = fmaf(p128_4, bu, bag);
    ts += __shfl_xor_sync(FULL, ts, 1); tq += __shfl_xor_sync(FULL, tq, 1);
    ts = __shfl_sync(FULL, ts, 0);
    tq = __shfl_sync(FULL, tq, 0);
    const float s0 = (tq - ts * ts * (1.0f / (float)T_LEN))
                     * (1.0f / (float)(T_LEN - 1));

    // segment base states + this warp's prefix, all via shuffles
    const int wp_lane = (wid > 0) ? (wid - 1) : 0;
    float S[NSEG];
    float b_wp[NSEG];
    S[0] = s0;
    #pragma unroll
    for (int j = 0; j < NSEG; j++) {
        float bfull = __shfl_sync(FULL, bag, j * 8 + 7);          // full segment aggregate
        float bw    = __shfl_sync(FULL, bag, j * 8 + wp_lane);    // prefix over warps < wid
        b_wp[j] = (wid > 0) ? bw : 0.0f;
        if (j < NSEG - 1) S[j + 1] = fmaf(beta1024, S[j], bfull);
    }

    // thread-exclusive b within warp
    float b_exc[NSEG];
    #pragma unroll
    for (int j = 0; j < NSEG; j++) {
        b_exc[j] = __shfl_up_sync(FULL, B[j], 1);
        if (lane == 0) b_exc[j] = 0.0f;
    }

    // ---- replay all 4 segments (independent chains -> MUFU/FMA ILP) ----
    #pragma unroll
    for (int j = 0; j < NSEG; j++) {
        float s = fmaf(a_tot, S[j], fmaf(a_exc, b_wp[j], b_exc[j]));

        float4 o;
        o.x = s * rsqrtf(s); s = fmaf(beta, s, c[j][0]);
        o.y = s * rsqrtf(s); s = fmaf(beta, s, c[j][1]);
        o.z = s * rsqrtf(s); s = fmaf(beta, s, c[j][2]);
        o.w = s * rsqrtf(s);

        __stcs(&out4[row4 + j * NTHREADS + tid], o);
    }
}

extern "C" void kernel_launch(void* const* d_in, const int* in_sizes, int n_in,
                              void* d_out, int out_size)
{
    const float4* x4       = (const float4*)d_in[0];
    const float* omega_log = (const float*)d_in[1];
    const float* alpha_log = (const float*)d_in[2];
    const float* beta_log  = (const float*)d_in[3];
    float4* out4 = (float4*)d_out;

    const int B = in_sizes[0] / T_LEN;   // 4096 rows
    garch_kernel<<<B, NTHREADS>>>(x4, omega_log, alpha_log, beta_log, out4);
}